// round 13
// baseline (speedup 1.0000x reference)
#include <cuda_runtime.h>
#include <cuda_fp16.h>
#include <stdint.h>

// ---------------- problem constants ----------------
#define D_IN    1024
#define D_OUT   1024
#define RANK    16
#define SCALING 2.0f          // alpha / rank = 32/16
#define M_MAX   32768         // B*S = 4*8192

// ---------------- GEMM tiling ----------------
#define TM      128
#define TN      128
#define KC      64            // k-chunk per stage
#define NCHUNK  (D_IN / KC)   // 16
#define STAGES  3
#define NTHR    128           // 4 warps: 2(M) x 2(N), warp tile 64x64

#define TILE_B  (TM * KC * 2)         // 16384 bytes (128 rows x 64 fp16)
#define S_A     0
#define S_B     TILE_B
#define STAGE_B (2 * TILE_B)          // 32768
#define SMEM_TOT (STAGES * STAGE_B)   // 98304 -> 2 CTAs/SM

// ---------------- device scratch (static: no allocs allowed) ----------------
__device__ __align__(128) __half g_wh[D_OUT * D_IN];

// ---------------- helpers ----------------
__device__ __forceinline__ uint32_t smem_u32(const void* p) {
    uint32_t a;
    asm("{ .reg .u64 t; cvta.to.shared.u64 t, %1; cvt.u32.u64 %0, t; }"
        : "=r"(a) : "l"(p));
    return a;
}

__device__ __forceinline__ void cp16(uint32_t saddr, const void* gptr) {
    asm volatile("cp.async.cg.shared.global [%0], [%1], 16;"
                 :: "r"(saddr), "l"(gptr) : "memory");
}
#define CP_COMMIT()  asm volatile("cp.async.commit_group;" ::: "memory")
#define CP_WAIT(n)   asm volatile("cp.async.wait_group %0;" :: "n"(n) : "memory")

#define LDSM4(R, addr)                                                        \
    asm volatile("ldmatrix.sync.aligned.m8n8.x4.shared.b16 {%0,%1,%2,%3}, [%4];" \
                 : "=r"((R)[0]), "=r"((R)[1]), "=r"((R)[2]), "=r"((R)[3])     \
                 : "r"(addr))

#define STS128(addr, a, b, c, d)                                              \
    asm volatile("st.shared.v4.b32 [%0], {%1, %2, %3, %4};"                   \
                 :: "r"(addr), "r"(a), "r"(b), "r"(c), "r"(d) : "memory")

// fp16 inputs, fp32 accumulate
#define MMA_F32(d, a, b0, b1)                                                 \
    asm volatile("mma.sync.aligned.m16n8k16.row.col.f32.f16.f16.f32 "         \
                 "{%0,%1,%2,%3}, {%4,%5,%6,%7}, {%8,%9}, {%0,%1,%2,%3};"      \
                 : "+f"((d)[0]), "+f"((d)[1]), "+f"((d)[2]), "+f"((d)[3])     \
                 : "r"((a)[0]), "r"((a)[1]), "r"((a)[2]), "r"((a)[3]),        \
                   "r"(b0), "r"(b1))

__device__ __forceinline__ uint32_t pack2h(float a, float b) {
    __half2 h = __floats2half2_rn(a, b);
    return *reinterpret_cast<uint32_t*>(&h);
}

// ---------------- prep: effective weight, scale-folded -> fp16 ----------------
__global__ void __launch_bounds__(256) dora_prep_kernel(
    const float* __restrict__ W, const float* __restrict__ a_w,
    const float* __restrict__ b_w, const float* __restrict__ mag) {
    const int o = blockIdx.x;
    const int t = threadIdx.x;

    __shared__ float b_sh[RANK];
    __shared__ float red[256];
    __shared__ float scale_sh;

    if (t < RANK) b_sh[t] = b_w[o * RANK + t];
    __syncthreads();

    float vals[4];
    float ss = 0.0f;
#pragma unroll
    for (int i = 0; i < 4; i++) {
        int d = t + i * 256;
        float acc = W[(size_t)o * D_IN + d];
        float l = 0.0f;
#pragma unroll
        for (int r = 0; r < RANK; r++)
            l += b_sh[r] * a_w[r * D_IN + d];
        acc += SCALING * l;
        vals[i] = acc;
        ss += acc * acc;
    }

    red[t] = ss;
    __syncthreads();
#pragma unroll
    for (int s = 128; s > 0; s >>= 1) {
        if (t < s) red[t] += red[t + s];
        __syncthreads();
    }
    if (t == 0) scale_sh = mag[o] / sqrtf(red[0]);
    __syncthreads();
    const float scale = scale_sh;

#pragma unroll
    for (int i = 0; i < 4; i++) {
        int d = t + i * 256;
        g_wh[(size_t)o * D_IN + d] = __float2half_rn(vals[i] * scale);
    }
}

// ---------------- GEMM: out[M,1024] = fp16(x) @ w_h^T (fp32 accum) ----------------
// CTA tile 128x128, 4 warps (2Mx2N), warp tile 64x64, 3-stage pipeline, 2 CTAs/SM.
// A tiles: x fp32 LDG -> cvt fp16 -> STS (fused conversion, no xsplit pass).
// B tiles: cp.async. Fence: CP_WAIT(1) -> __syncthreads -> reads.
__global__ void __launch_bounds__(NTHR, 2) dora_gemm_kernel(
    const float* __restrict__ x, float* __restrict__ out) {
    extern __shared__ char smem_raw[];
    const uint32_t sb = smem_u32(smem_raw);

    const int tid  = threadIdx.x;
    const int lane = tid & 31;
    const int warp = tid >> 5;
    const int n0 = blockIdx.x * TN;
    const int m0 = blockIdx.y * TM;

    // ---- tile load addressing ----
    // tile rows are 128B (64 fp16); swizzle: byte ^ ((row&7)<<4).
    // thread handles chunk (row = (tid>>3)+16i, 16B col block c8 = tid&7);
    // smem offset advances by exactly 2048 per i (row&7 constant).
    const uint32_t soff0 = (uint32_t)((tid >> 3) * 128 +
                           (((tid & 7) * 16) ^ (((tid >> 3) & 7) << 4)));
    const float*  gx0 = x    + (size_t)(m0 + (tid >> 3)) * D_IN + (tid & 7) * 8;
    const __half* gB0 = g_wh + (size_t)(n0 + (tid >> 3)) * D_IN + (tid & 7) * 8;

#define LOAD_B_STAGE(kc_, slot_)                                             \
    do {                                                                     \
        uint32_t k0_ = (uint32_t)(kc_) * KC;                                 \
        uint32_t b_ = sb + (uint32_t)(slot_) * STAGE_B + S_B;                \
        _Pragma("unroll")                                                    \
        for (int i_ = 0; i_ < 8; i_++)                                       \
            cp16(b_ + soff0 + i_ * 2048, gB0 + i_ * 16 * D_IN + k0_);        \
    } while (0)

// load 4 row-groups (i0..i0+3) of x fp32 into v[8] (float4)
#define LDG_A4(v, kc_, i0_)                                                  \
    do {                                                                     \
        const float* p_ = gx0 + (uint32_t)(kc_) * KC;                        \
        _Pragma("unroll")                                                    \
        for (int j_ = 0; j_ < 4; j_++) {                                     \
            (v)[2 * j_]     = *reinterpret_cast<const float4*>(              \
                                  p_ + ((i0_) + j_) * 16 * D_IN);            \
            (v)[2 * j_ + 1] = *reinterpret_cast<const float4*>(              \
                                  p_ + ((i0_) + j_) * 16 * D_IN + 4);        \
        }                                                                    \
    } while (0)

// convert v[8] -> fp16, store 4 row-groups into A tile of slot_
#define STS_A4(v, slot_, i0_)                                                \
    do {                                                                     \
        uint32_t b_ = sb + (uint32_t)(slot_) * STAGE_B + S_A + soff0;        \
        _Pragma("unroll")                                                    \
        for (int j_ = 0; j_ < 4; j_++) {                                     \
            uint32_t w0_ = pack2h((v)[2 * j_].x, (v)[2 * j_].y);             \
            uint32_t w1_ = pack2h((v)[2 * j_].z, (v)[2 * j_].w);             \
            uint32_t w2_ = pack2h((v)[2 * j_ + 1].x, (v)[2 * j_ + 1].y);     \
            uint32_t w3_ = pack2h((v)[2 * j_ + 1].z, (v)[2 * j_ + 1].w);     \
            STS128(b_ + ((i0_) + j_) * 2048, w0_, w1_, w2_, w3_);            \
        }                                                                    \
    } while (0)

    // ---- warp tiling: 2 (M) x 2 (N); warp tile 64x64 ----
    const int wm = warp & 1;
    const int wn = warp >> 1;
    const int q = lane >> 3;
    const int r = lane & 7;

    const uint32_t rx   = (uint32_t)(r << 4);
    const uint32_t a_b0 = (uint32_t)((wm * 64 + (q & 1) * 8 + r) * 128);
    const uint32_t b_b0 = (uint32_t)((wn * 64 + (q >> 1) * 8 + r) * 128);
    const uint32_t a_kb = (uint32_t)((q >> 1) * 16);
    const uint32_t b_kb = (uint32_t)((q & 1) * 16);

    float acc[4][8][4];
#pragma unroll
    for (int mt = 0; mt < 4; mt++)
#pragma unroll
        for (int nt = 0; nt < 8; nt++)
#pragma unroll
            for (int j = 0; j < 4; j++) acc[mt][nt][j] = 0.0f;

// one k-step: LDSM fragments + 32 MMAs
#define KSTEP(ks_)                                                           \
    do {                                                                     \
        const uint32_t ao_ = aA + ((a_kb + (ks_) * 32) ^ rx);                \
        const uint32_t bo_ = aB + ((b_kb + (ks_) * 32) ^ rx);                \
        uint32_t Af_[4][4], Bf_[4][4];                                       \
        _Pragma("unroll")                                                    \
        for (int mt_ = 0; mt_ < 4; mt_++) LDSM4(Af_[mt_], ao_ + mt_ * 2048); \
        _Pragma("unroll")                                                    \
        for (int bt_ = 0; bt_ < 4; bt_++) LDSM4(Bf_[bt_], bo_ + bt_ * 2048); \
        _Pragma("unroll")                                                    \
        for (int mt_ = 0; mt_ < 4; mt_++) {                                  \
            _Pragma("unroll")                                                \
            for (int nt_ = 0; nt_ < 8; nt_++) {                              \
                const int bt_ = nt_ >> 1, s_ = (nt_ & 1) * 2;                \
                MMA_F32(acc[mt_][nt_], Af_[mt_], Bf_[bt_][s_],               \
                        Bf_[bt_][s_ + 1]);                                   \
            }                                                                \
        }                                                                    \
    } while (0)

    // ---- prologue: build A tiles for chunks 0,1 (LDG+cvt+STS), B via cp.async ----
    {
        float4 v[8];
#pragma unroll
        for (int c = 0; c < 2; c++) {
            LDG_A4(v, c, 0); STS_A4(v, c, 0);
            LDG_A4(v, c, 4); STS_A4(v, c, 4);
        }
    }
    LOAD_B_STAGE(0, 0); CP_COMMIT();
    LOAD_B_STAGE(1, 1); CP_COMMIT();

    for (int kc = 0; kc < NCHUNK; kc++) {
        CP_WAIT(1);          // B group for chunk kc complete (only kc+1 pending)
        __syncthreads();     // publish copies/stores; slot (kc+2)%3 free

        const int doload = (kc + 2 < NCHUNK);
        const int slot2  = (kc + 2) % STAGES;
        if (doload) LOAD_B_STAGE(kc + 2, slot2);
        CP_COMMIT();         // uniform group count

        const uint32_t sbase = sb + (uint32_t)(kc % STAGES) * STAGE_B;
        const uint32_t aA = sbase + S_A + a_b0;
        const uint32_t aB = sbase + S_B + b_b0;

        float4 v[8];
        if (doload) LDG_A4(v, kc + 2, 0);     // batch 1 in flight
        KSTEP(0);                             // ~512 cyc of MMAs cover LDG
        if (doload) { STS_A4(v, slot2, 0); LDG_A4(v, kc + 2, 4); }
        KSTEP(1);
        KSTEP(2);
        if (doload) STS_A4(v, slot2, 4);
        KSTEP(3);
    }

    // ---- epilogue: direct global stores ----
    const int gm = lane >> 2;
    const int gn = (lane & 3) * 2;
#pragma unroll
    for (int mt = 0; mt < 4; mt++) {
#pragma unroll
        for (int nt = 0; nt < 8; nt++) {
            const int m = m0 + wm * 64 + mt * 16 + gm;
            const int n = n0 + wn * 64 + nt * 8 + gn;
            float2* p0 = reinterpret_cast<float2*>(out + (size_t)m * D_OUT + n);
            float2* p1 = reinterpret_cast<float2*>(out + (size_t)(m + 8) * D_OUT + n);
            *p0 = make_float2(acc[mt][nt][0], acc[mt][nt][1]);
            *p1 = make_float2(acc[mt][nt][2], acc[mt][nt][3]);
        }
    }
}

// ---------------- launch ----------------
extern "C" void kernel_launch(void* const* d_in, const int* in_sizes, int n_in,
                              void* d_out, int out_size) {
    const float* x   = (const float*)d_in[0];   // [B,S,D_IN]
    const float* W   = (const float*)d_in[1];   // [D_OUT, D_IN]
    const float* a_w = (const float*)d_in[2];   // [R, D_IN]
    const float* b_w = (const float*)d_in[3];   // [D_OUT, R]
    const float* mag = (const float*)d_in[4];   // [1, D_OUT]
    float* out = (float*)d_out;

    const int M = in_sizes[0] / D_IN;           // 32768

    dora_prep_kernel<<<D_OUT, 256>>>(W, a_w, b_w, mag);

    cudaFuncSetAttribute(dora_gemm_kernel,
                         cudaFuncAttributeMaxDynamicSharedMemorySize, SMEM_TOT);
    dim3 grid(D_OUT / TN, M / TM);              // (8, 256) — n fastest: x L2 reuse
    dora_gemm_kernel<<<grid, NTHR, SMEM_TOT>>>(x, out);
}

// round 14
// speedup vs baseline: 1.2123x; 1.2123x over previous
#include <cuda_runtime.h>
#include <cuda_fp16.h>
#include <stdint.h>

// ---------------- problem constants ----------------
#define D_IN    1024
#define D_OUT   1024
#define RANK    16
#define SCALING 2.0f          // alpha / rank = 32/16
#define M_MAX   32768         // B*S = 4*8192

// ---------------- GEMM tiling ----------------
#define TM      128
#define TN      128
#define KC      64            // k-chunk per stage
#define NCHUNK  (D_IN / KC)   // 16
#define STAGES  3
#define NTHR    128           // 4 warps: 2(M) x 2(N), warp tile 64x64
#define GRID_P  296           // persistent CTAs: 2 per SM x 148 SMs
#define NTILES  ((M_MAX / TM) * (D_OUT / TN))   // 2048

#define TILE_B  (TM * KC * 2)         // 16384 bytes (128 rows x 64 fp16)
#define S_A     0
#define S_B     TILE_B
#define STAGE_B (2 * TILE_B)          // 32768
#define SMEM_TOT (STAGES * STAGE_B)   // 98304 -> 2 CTAs/SM

// ---------------- device scratch (static: no allocs allowed) ----------------
__device__ __align__(128) __half g_wh[D_OUT * D_IN];
__device__ __align__(128) __half g_xh[(size_t)M_MAX * D_IN];

// ---------------- helpers ----------------
__device__ __forceinline__ uint32_t smem_u32(const void* p) {
    uint32_t a;
    asm("{ .reg .u64 t; cvta.to.shared.u64 t, %1; cvt.u32.u64 %0, t; }"
        : "=r"(a) : "l"(p));
    return a;
}

__device__ __forceinline__ void cp16(uint32_t saddr, const void* gptr) {
    asm volatile("cp.async.cg.shared.global [%0], [%1], 16;"
                 :: "r"(saddr), "l"(gptr) : "memory");
}
#define CP_COMMIT()  asm volatile("cp.async.commit_group;" ::: "memory")
#define CP_WAIT(n)   asm volatile("cp.async.wait_group %0;" :: "n"(n) : "memory")

#define LDSM4(R, addr)                                                        \
    asm volatile("ldmatrix.sync.aligned.m8n8.x4.shared.b16 {%0,%1,%2,%3}, [%4];" \
                 : "=r"((R)[0]), "=r"((R)[1]), "=r"((R)[2]), "=r"((R)[3])     \
                 : "r"(addr))

// fp16 inputs, fp32 accumulate
#define MMA_F32(d, a, b0, b1)                                                 \
    asm volatile("mma.sync.aligned.m16n8k16.row.col.f32.f16.f16.f32 "         \
                 "{%0,%1,%2,%3}, {%4,%5,%6,%7}, {%8,%9}, {%0,%1,%2,%3};"      \
                 : "+f"((d)[0]), "+f"((d)[1]), "+f"((d)[2]), "+f"((d)[3])     \
                 : "r"((a)[0]), "r"((a)[1]), "r"((a)[2]), "r"((a)[3]),        \
                   "r"(b0), "r"(b1))

// ---------------- fused prep: weight fold (blocks 0..1023) + x convert (rest) ----------------
__global__ void __launch_bounds__(256) fused_prep_kernel(
    const float* __restrict__ W, const float* __restrict__ a_w,
    const float* __restrict__ b_w, const float* __restrict__ mag,
    const float* __restrict__ x, int total8) {
    const int t = threadIdx.x;

    if (blockIdx.x < D_OUT) {
        const int o = blockIdx.x;
        __shared__ float b_sh[RANK];
        __shared__ float red[256];
        __shared__ float scale_sh;

        if (t < RANK) b_sh[t] = b_w[o * RANK + t];
        __syncthreads();

        float vals[4];
        float ss = 0.0f;
#pragma unroll
        for (int i = 0; i < 4; i++) {
            int d = t + i * 256;
            float acc = W[(size_t)o * D_IN + d];
            float l = 0.0f;
#pragma unroll
            for (int r = 0; r < RANK; r++)
                l += b_sh[r] * a_w[r * D_IN + d];
            acc += SCALING * l;
            vals[i] = acc;
            ss += acc * acc;
        }

        red[t] = ss;
        __syncthreads();
#pragma unroll
        for (int s = 128; s > 0; s >>= 1) {
            if (t < s) red[t] += red[t + s];
            __syncthreads();
        }
        if (t == 0) scale_sh = mag[o] / sqrtf(red[0]);
        __syncthreads();
        const float scale = scale_sh;

#pragma unroll
        for (int i = 0; i < 4; i++) {
            int d = t + i * 256;
            g_wh[(size_t)o * D_IN + d] = __float2half_rn(vals[i] * scale);
        }
    } else {
        int i = (blockIdx.x - D_OUT) * 256 + t;
        if (i >= total8) return;
        size_t base = (size_t)i * 8;
        float4 v0 = *reinterpret_cast<const float4*>(x + base);
        float4 v1 = *reinterpret_cast<const float4*>(x + base + 4);
        __half2 h0 = __floats2half2_rn(v0.x, v0.y);
        __half2 h1 = __floats2half2_rn(v0.z, v0.w);
        __half2 h2 = __floats2half2_rn(v1.x, v1.y);
        __half2 h3 = __floats2half2_rn(v1.z, v1.w);
        *reinterpret_cast<uint4*>(g_xh + base) = make_uint4(
            *reinterpret_cast<uint32_t*>(&h0), *reinterpret_cast<uint32_t*>(&h1),
            *reinterpret_cast<uint32_t*>(&h2), *reinterpret_cast<uint32_t*>(&h3));
    }
}

// ---------------- GEMM: out[M,1024] = x_h @ w_h^T (fp32 accum) ----------------
// Persistent CTAs (296): each loops over tiles bid, bid+296, ... with a
// CONTINUOUS 3-stage cp.async pipeline across tile boundaries.
// CTA tile 128x128, 4 warps (2Mx2N), warp tile 64x64, k-step frag double-buffer.
// Fence invariant per virtual chunk v: CP_WAIT(1) -> __syncthreads -> loads.
__global__ void __launch_bounds__(NTHR, 2) dora_gemm_kernel(float* __restrict__ out) {
    extern __shared__ char smem_raw[];
    const uint32_t sb = smem_u32(smem_raw);

    const int tid  = threadIdx.x;
    const int lane = tid & 31;
    const int warp = tid >> 5;
    const int bid  = blockIdx.x;

    // ---- tile-load addressing (per thread, tile-independent parts) ----
    // tile rows are 128B (64 fp16); swizzle: byte ^ ((row&7)<<4).
    const uint32_t soff0 = (uint32_t)((tid >> 3) * 128 +
                           (((tid & 7) * 16) ^ (((tid >> 3) & 7) << 4)));
    const int rowA = tid >> 3;          // 0..15 (row group base)
    const int colc = (tid & 7) * 8;     // element column within row

    // number of tiles for this CTA; virtual chunks v = 0 .. VMAX-1
    const int ntl  = (NTILES - bid + GRID_P - 1) / GRID_P;
    const int VMAX = ntl * NCHUNK;

// issue cp.async for virtual chunk v_ into slot (v_)%3
#define LOAD_V(v_)                                                           \
    do {                                                                     \
        int t_  = bid + ((v_) >> 4) * GRID_P;                                \
        int kc_ = (v_) & 15;                                                 \
        int m0_ = (t_ >> 3) * TM;                                            \
        int n0_ = (t_ & 7) * TN;                                             \
        const __half* gA_ = g_xh + (((size_t)(m0_ + rowA)) << 10)            \
                                 + colc + kc_ * KC;                          \
        const __half* gB_ = g_wh + (((size_t)(n0_ + rowA)) << 10)            \
                                 + colc + kc_ * KC;                          \
        uint32_t b_ = sb + (uint32_t)((v_) % 3) * STAGE_B;                   \
        _Pragma("unroll")                                                    \
        for (int i_ = 0; i_ < 8; i_++) {                                     \
            cp16(b_ + S_A + soff0 + i_ * 2048, gA_ + i_ * 16 * D_IN);        \
            cp16(b_ + S_B + soff0 + i_ * 2048, gB_ + i_ * 16 * D_IN);        \
        }                                                                    \
    } while (0)

    // ---- warp tiling: 2 (M) x 2 (N); warp tile 64x64 ----
    const int wm = warp & 1;
    const int wn = warp >> 1;
    const int q = lane >> 3;
    const int r = lane & 7;

    const uint32_t rx   = (uint32_t)(r << 4);
    const uint32_t a_b0 = (uint32_t)((wm * 64 + (q & 1) * 8 + r) * 128);
    const uint32_t b_b0 = (uint32_t)((wn * 64 + (q >> 1) * 8 + r) * 128);
    const uint32_t a_kb = (uint32_t)((q >> 1) * 16);
    const uint32_t b_kb = (uint32_t)((q & 1) * 16);

    float acc[4][8][4];
#pragma unroll
    for (int mt = 0; mt < 4; mt++)
#pragma unroll
        for (int nt = 0; nt < 8; nt++)
#pragma unroll
            for (int j = 0; j < 4; j++) acc[mt][nt][j] = 0.0f;

    uint32_t A[2][4][4];
    uint32_t B[2][4][4];

    const int gm = lane >> 2;
    const int gn = (lane & 3) * 2;

    // ---- prologue: prefetch v=0,1 ----
    LOAD_V(0); CP_COMMIT();
    LOAD_V(1); CP_COMMIT();

    int slot = 0;   // = v % 3
    for (int v = 0; v < VMAX; v++) {
        CP_WAIT(1);          // group v complete (only v+1 pending)
        __syncthreads();     // publish copies; slot (v+2)%3 free

        if (v + 2 < VMAX) LOAD_V(v + 2);
        CP_COMMIT();         // uniform group count

        const uint32_t sbase = sb + (uint32_t)slot * STAGE_B;
        const uint32_t aA = sbase + S_A + a_b0;
        const uint32_t aB = sbase + S_B + b_b0;

        // k-step 0 fragments into buffer 0
        {
            const uint32_t ao = aA + (a_kb ^ rx);
            const uint32_t bo = aB + (b_kb ^ rx);
#pragma unroll
            for (int mt = 0; mt < 4; mt++) LDSM4(A[0][mt], ao + mt * 2048);
#pragma unroll
            for (int bt = 0; bt < 4; bt++) LDSM4(B[0][bt], bo + bt * 2048);
        }

#pragma unroll
        for (int ks = 0; ks < 4; ks++) {
            const int cur = ks & 1;
            const int nxt = cur ^ 1;
            if (ks < 3) {   // prefetch next k-step while MMAs run
                const uint32_t ao = aA + ((a_kb + (ks + 1) * 32) ^ rx);
                const uint32_t bo = aB + ((b_kb + (ks + 1) * 32) ^ rx);
#pragma unroll
                for (int mt = 0; mt < 4; mt++) LDSM4(A[nxt][mt], ao + mt * 2048);
#pragma unroll
                for (int bt = 0; bt < 4; bt++) LDSM4(B[nxt][bt], bo + bt * 2048);
            }
#pragma unroll
            for (int mt = 0; mt < 4; mt++) {
#pragma unroll
                for (int nt = 0; nt < 8; nt++) {
                    const int bt = nt >> 1, s = (nt & 1) * 2;
                    MMA_F32(acc[mt][nt], A[cur][mt], B[cur][bt][s], B[cur][bt][s + 1]);
                }
            }
        }

        slot++; if (slot == 3) slot = 0;

        // ---- tile finished: epilogue + reset accumulators ----
        if ((v & 15) == 15) {
            const int t_  = bid + (v >> 4) * GRID_P;
            const int m0_ = (t_ >> 3) * TM;
            const int n0_ = (t_ & 7) * TN;
#pragma unroll
            for (int mt = 0; mt < 4; mt++) {
#pragma unroll
                for (int nt = 0; nt < 8; nt++) {
                    const int m = m0_ + wm * 64 + mt * 16 + gm;
                    const int n = n0_ + wn * 64 + nt * 8 + gn;
                    float2* p0 = reinterpret_cast<float2*>(out + (size_t)m * D_OUT + n);
                    float2* p1 = reinterpret_cast<float2*>(out + (size_t)(m + 8) * D_OUT + n);
                    *p0 = make_float2(acc[mt][nt][0], acc[mt][nt][1]);
                    *p1 = make_float2(acc[mt][nt][2], acc[mt][nt][3]);
#pragma unroll
                    for (int j = 0; j < 4; j++) acc[mt][nt][j] = 0.0f;
                }
            }
        }
    }
}

// ---------------- launch ----------------
extern "C" void kernel_launch(void* const* d_in, const int* in_sizes, int n_in,
                              void* d_out, int out_size) {
    const float* x   = (const float*)d_in[0];   // [B,S,D_IN]
    const float* W   = (const float*)d_in[1];   // [D_OUT, D_IN]
    const float* a_w = (const float*)d_in[2];   // [R, D_IN]
    const float* b_w = (const float*)d_in[3];   // [D_OUT, R]
    const float* mag = (const float*)d_in[4];   // [1, D_OUT]
    float* out = (float*)d_out;

    const int M = in_sizes[0] / D_IN;           // 32768
    const int total8 = M * D_IN / 8;
    const int xblocks = (total8 + 255) / 256;

    fused_prep_kernel<<<D_OUT + xblocks, 256>>>(W, a_w, b_w, mag, x, total8);

    cudaFuncSetAttribute(dora_gemm_kernel,
                         cudaFuncAttributeMaxDynamicSharedMemorySize, SMEM_TOT);
    dora_gemm_kernel<<<GRID_P, NTHR, SMEM_TOT>>>(out);
}